// round 14
// baseline (speedup 1.0000x reference)
#include <cuda_runtime.h>
#include <math.h>
#include <stdint.h>

#define Bb 2048
#define Mm 64
#define Dd 512
#define NROWS (Bb*Mm)     // 131072
#define NC    2560        // stacked cols: [zr | zw | zF | interleaved(zI,zC)]
#define BM    128
#define BN    128
#define BK    32
#define NKC   (Dd/BK)     // 16
#define STG   2
#define PAD   36          // floats per smem row (144B; conflict-free LDSM)
#define ASTG  (128*PAD)   // 4608 floats
#define BSTG  (128*PAD)
#define XTSOFF (STG*(ASTG+BSTG))          // dedicated epilogue staging
#define SMEM_BYTES ((XTSOFF + 384)*4)     // 75264 B -> 3 CTAs/SM

// ---------------- scratch (device globals) -----------------------------------------
__device__ float g_Wbig [NC*Dd];
__device__ float g_WbigX[NC*Dd];
__device__ float g_bstack[NC];
__device__ float g_xterm[Bb*NC];
__device__ float g_F[(size_t)NROWS*Dd];
__device__ float g_P[(size_t)NROWS*Dd];      // sigmoid(zI)*tanh(zC)
__device__ float g_subvec[Bb*Dd];
__device__ float g_sRp[(size_t)NROWS*8];
__device__ float g_sWp[(size_t)NROWS*8];
__device__ float g_simr[NROWS];
__device__ float g_simw[NROWS];

__device__ __forceinline__ uint32_t smem_u32(const void* p){
    uint32_t a;
    asm("{ .reg .u64 t; cvta.to.shared.u64 t, %1; cvt.u32.u64 %0, t; }" : "=r"(a) : "l"(p));
    return a;
}
__device__ __forceinline__ float fsig(float z){ return __fdividef(1.f, 1.f + __expf(-z)); }
__device__ __forceinline__ float ftanh(float z){ return __fdividef(2.f, 1.f + __expf(-2.f*z)) - 1.f; }
__device__ __forceinline__ void ldmx4(uint32_t* r, uint32_t addr){
    asm volatile("ldmatrix.sync.aligned.m8n8.x4.shared.b16 {%0,%1,%2,%3}, [%4];"
        : "=r"(r[0]), "=r"(r[1]), "=r"(r[2]), "=r"(r[3]) : "r"(addr));
}
__device__ __forceinline__ void mma8(float* d, const uint32_t* a, const uint32_t* b){
    asm volatile(
        "mma.sync.aligned.m16n8k8.row.col.f32.tf32.tf32.f32 "
        "{%0,%1,%2,%3}, {%4,%5,%6,%7}, {%8,%9}, {%0,%1,%2,%3};"
        : "+f"(d[0]), "+f"(d[1]), "+f"(d[2]), "+f"(d[3])
        : "r"(a[0]), "r"(a[1]), "r"(a[2]), "r"(a[3]), "r"(b[0]), "r"(b[1]));
}

// ---------------- weight stacking: [Wr | Ww | WF | interleave(WI,WC)] ----------------
__global__ void prep_k(const float* __restrict__ W1r, const float* __restrict__ W1w,
                       const float* __restrict__ Wf,  const float* __restrict__ Wi,
                       const float* __restrict__ Wc,
                       const float* __restrict__ b1r, const float* __restrict__ b1w,
                       const float* __restrict__ bf,  const float* __restrict__ bi,
                       const float* __restrict__ bc)
{
    int i = blockIdx.x*blockDim.x + threadIdx.x;
    if (i < NC*Dd) {
        int c = i >> 9, k = i & 511;
        const float* W; int d;
        if (c < 1536) { int j = c >> 9; d = c & 511; W = (j==0)?W1r:(j==1)?W1w:Wf; }
        else          { int t = c - 1536; d = t >> 1; W = (t&1)?Wc:Wi; }
        g_Wbig[i]  = W[d*(2*Dd) + k];
        g_WbigX[i] = W[d*(2*Dd) + Dd + k];
        if (i < NC) {
            const float* bb; int db;
            if (i < 1536) { int j = i >> 9; db = i & 511; bb = (j==0)?b1r:(j==1)?b1w:bf; }
            else          { int t = i - 1536; db = t >> 1; bb = (t&1)?bc:bi; }
            g_bstack[i] = bb[db];
        }
    }
}

// ---------------- tf32 mma.sync GEMM, 64x64 warp tiles, 128 thr, 3 CTAs/SM ------------
// Spill-free schedule: B frags resident per k-step, A streamed per m-tile.
// epi 0: xterm   epi 1: main (scores / F / P)   epi 2: fin->out
// epi 3: sub->out with FUSED gating in the A loader
__global__ void __launch_bounds__(128,3)
gemm_t(int epi, const float* __restrict__ Aext, const float* __restrict__ Bext,
       const float* __restrict__ bias,
       const float* __restrict__ w2r, const float* __restrict__ w2w,
       float* __restrict__ out)
{
    extern __shared__ float sm[];
    const uint32_t s0 = smem_u32(sm);

    const int tid  = threadIdx.x;
    const int lane = tid & 31, wid = tid >> 5;   // 4 warps
    const int wm = wid & 1, wn = wid >> 1;       // 2x2 warp grid, warp tile 64x64
    const int qrow = lane >> 2;
    const int qcol = (lane & 3) * 2;
    const int row0 = blockIdx.y * BM;
    const int n0   = blockIdx.x * BN;
    const int jt   = n0 >> 9;                    // epi1: 0,1=scores(r,w) 2=F 3,4=IC

    const float* A  = (epi==2) ? g_subvec : Aext;
    const float* Bw = (epi==0) ? g_WbigX : (epi==1) ? g_Wbig : Bext;

    const float* Arow = A  + (size_t)row0 * Dd;
    const float* Brow = Bw + (size_t)n0   * Dd;

    float* xts = sm + XTSOFF;        // [2][128]
    float* w2s = sm + XTSOFF + 256;  // [128]

    // pre-stage epilogue inputs (visible after mainloop barriers)
    if (epi == 1) {
#pragma unroll
        for (int t=0;t<2;t++){
            int idx = t*128 + tid;
            int bloc = idx >> 7, cl = idx & 127;
            xts[idx] = g_xterm[(size_t)((row0 >> 6) + bloc) * NC + n0 + cl];
        }
        if (jt < 2) w2s[tid] = ((jt==0)?w2r:w2w)[(n0 & 511) + tid];
    }

    float acc[4][8][4];
#pragma unroll
    for (int mt=0;mt<4;mt++)
#pragma unroll
        for (int nt=0;nt<8;nt++)
#pragma unroll
            for (int q=0;q<4;q++) acc[mt][nt][q]=0.f;

    // base ldmatrix byte offsets; per-tile displacement is a compile-time constant
    const uint32_t offA0 = (uint32_t)(((wm*64 + (lane&15))*PAD + ((lane>>4)<<2)) * 4);
    const uint32_t offB0 = (uint32_t)(((wn*64 + (((lane>>4)&1)<<3) + (lane&7))*PAD
                                       + (((lane>>3)&1)<<2)) * 4);

#define LOADA(kc, slot) do {                                                     \
    int k0 = (kc)*BK;                                                            \
    _Pragma("unroll")                                                            \
    for (int j=0;j<8;j++){                                                       \
        int idx = j*128 + tid;                                                   \
        int r = idx >> 3, seg = idx & 7;                                         \
        const float* ga = Arow + (size_t)r*Dd + k0 + seg*4;                      \
        uint32_t sa = s0 + (uint32_t)(((slot)*ASTG + r*PAD + seg*4)*4);          \
        asm volatile("cp.async.cg.shared.global [%0],[%1],16;" :: "r"(sa), "l"(ga)); \
    } } while(0)

#define LOADA3(kc, slot) do {                                                    \
    int k0 = (kc)*BK;                                                            \
    _Pragma("unroll")                                                            \
    for (int j=0;j<8;j++){                                                       \
        int idx = j*128 + tid;                                                   \
        int r = idx >> 3, seg = idx & 7;                                         \
        int grow = row0 + r;                                                     \
        size_t goff = (size_t)grow*Dd + k0 + seg*4;                              \
        float swv = __ldg(g_simw + grow);                                        \
        float4 s4 = *(const float4*)(Arow + (size_t)r*Dd + k0 + seg*4);          \
        float4 fv = *(const float4*)(g_F + goff);                                \
        float4 pv = *(const float4*)(g_P + goff);                                \
        float4 o;                                                                \
        o.x = (1.f - swv*fv.x)*s4.x + pv.x*swv;                                  \
        o.y = (1.f - swv*fv.y)*s4.y + pv.y*swv;                                  \
        o.z = (1.f - swv*fv.z)*s4.z + pv.z*swv;                                  \
        o.w = (1.f - swv*fv.w)*s4.w + pv.w*swv;                                  \
        *(float4*)(sm + (slot)*ASTG + r*PAD + seg*4) = o;                        \
    } } while(0)

#define LOADB(kc, slot) do {                                                     \
    int k0 = (kc)*BK;                                                            \
    _Pragma("unroll")                                                            \
    for (int j=0;j<8;j++){                                                       \
        int idx = j*128 + tid;                                                   \
        int r = idx >> 3, seg = idx & 7;                                         \
        const float* gb = Brow + (size_t)r*Dd + k0 + seg*4;                      \
        uint32_t sb = s0 + (uint32_t)(((STG*ASTG) + (slot)*BSTG + r*PAD + seg*4)*4); \
        asm volatile("cp.async.cg.shared.global [%0],[%1],16;" :: "r"(sb), "l"(gb)); \
    }                                                                            \
    asm volatile("cp.async.commit_group;" ::: "memory");                         \
} while(0)

    if (epi != 3) LOADA(0,0); else LOADA3(0,0);
    LOADB(0,0);

    for (int i = 0; i < NKC; i++) {
        int slot = i & 1;
        asm volatile("cp.async.wait_group 0;" ::: "memory");
        __syncthreads();
        if (i + 1 < NKC) {
            int ns = slot ^ 1;
            if (epi != 3) LOADA(i+1, ns); else LOADA3(i+1, ns);
            LOADB(i+1, ns);
        }

        uint32_t abase = s0 + (uint32_t)(slot*ASTG*4) + offA0;
        uint32_t bbase = s0 + (uint32_t)((STG*ASTG + slot*BSTG)*4) + offB0;
#pragma unroll
        for (int s = 0; s < 4; s++) {               // four k8 steps
            // B fragments resident for this step (16 regs)
            uint32_t bt[4][4];
#pragma unroll
            for (int p=0;p<4;p++)
                ldmx4(bt[p], bbase + (uint32_t)(p*16*PAD*4) + s*32);
            // stream A one m-tile at a time (4 regs live)
#pragma unroll
            for (int mt=0;mt<4;mt++){
                uint32_t a[4];
                ldmx4(a, abase + (uint32_t)(mt*16*PAD*4) + s*32);
#pragma unroll
                for (int p=0;p<4;p++){
                    mma8(acc[mt][2*p],   a, &bt[p][0]);
                    mma8(acc[mt][2*p+1], a, &bt[p][2]);
                }
            }
        }
    }
#undef LOADA
#undef LOADA3
#undef LOADB

    // ---------------- epilogue (xts/w2s pre-staged) -------------------------------------
    if (epi == 1 && jt < 2) {
        float* dstp = (jt == 0) ? g_sRp : g_sWp;
        const int pidx = ((n0 & 511) >> 7) * 2 + wn;      // 0..7
        const float* x0 = xts + wm * 128;
#pragma unroll
        for (int mt=0;mt<4;mt++){
            int r0g = row0 + wm*64 + mt*16 + qrow;
            float sp0 = 0.f, sp1 = 0.f;
#pragma unroll
            for (int nt=0;nt<8;nt++){
                int cl = wn*64 + nt*8 + qcol;
                float w0 = w2s[cl], w1 = w2s[cl+1];
                sp0 += fmaxf(acc[mt][nt][0]+x0[cl],0.f)*w0 + fmaxf(acc[mt][nt][1]+x0[cl+1],0.f)*w1;
                sp1 += fmaxf(acc[mt][nt][2]+x0[cl],0.f)*w0 + fmaxf(acc[mt][nt][3]+x0[cl+1],0.f)*w1;
            }
            sp0 += __shfl_xor_sync(0xffffffffu, sp0, 1);
            sp0 += __shfl_xor_sync(0xffffffffu, sp0, 2);
            sp1 += __shfl_xor_sync(0xffffffffu, sp1, 1);
            sp1 += __shfl_xor_sync(0xffffffffu, sp1, 2);
            if ((lane & 3) == 0) {
                dstp[(size_t)r0g*8 + pidx]     = sp0;
                dstp[(size_t)(r0g+8)*8 + pidx] = sp1;
            }
        }
        return;
    }

#pragma unroll
    for (int mt=0;mt<4;mt++){
        int r0g = row0 + wm*64 + mt*16 + qrow;
#pragma unroll
        for (int h=0;h<2;h++){
            int row = r0g + h*8;
#pragma unroll
            for (int nt=0;nt<8;nt++){
                int cl = wn*64 + nt*8 + qcol;
                int cg = n0 + cl;
                float c0 = acc[mt][nt][h*2+0];
                float c1 = acc[mt][nt][h*2+1];
                if (epi == 0) {
                    float2 o = { c0 + bias[cg], c1 + bias[cg+1] };
                    *(float2*)(g_xterm + (size_t)row*NC + cg) = o;
                } else if (epi == 1) {
                    const float* xr = xts + wm * 128;
                    float z0 = c0 + xr[cl];
                    float z1 = c1 + xr[cl+1];
                    if (jt == 2) {
                        float2 o = { fsig(z0), fsig(z1) };
                        *(float2*)(g_F + (size_t)row*Dd + (cg - 1024)) = o;
                    } else {
                        g_P[(size_t)row*Dd + ((cg - 1536) >> 1)] = fsig(z0) * ftanh(z1);
                    }
                } else {
                    size_t ob = (epi == 2) ? (size_t)row * (65*Dd)
                                           : ((size_t)(row >> 6) * 65 + 1 + (row & 63)) * Dd;
                    float2 o = { ftanh(c0 + bias[cg]), ftanh(c1 + bias[cg+1]) };
                    *(float2*)(out + ob + cg) = o;
                }
            }
        }
    }
}

// ---------------- softmax over M=64 ---------------------------------------------------
__global__ void softmax_k() {
    int b = blockIdx.x, m = threadIdx.x;
    int row = b*64 + m;
    float sr = 0.f, sw = 0.f;
#pragma unroll
    for (int p=0;p<8;p++){ sr += g_sRp[(size_t)row*8+p]; sw += g_sWp[(size_t)row*8+p]; }

    __shared__ float sh[64];
    sh[m] = sr; __syncthreads();
    for (int s=32;s>0;s>>=1){ if(m<s) sh[m]=fmaxf(sh[m],sh[m+s]); __syncthreads(); }
    float mxr = sh[0]; __syncthreads();
    float er = expf(sr - mxr);
    sh[m] = er; __syncthreads();
    for (int s=32;s>0;s>>=1){ if(m<s) sh[m]+=sh[m+s]; __syncthreads(); }
    float sumr = sh[0]; __syncthreads();
    g_simr[row] = er / sumr;

    sh[m] = sw; __syncthreads();
    for (int s=32;s>0;s>>=1){ if(m<s) sh[m]=fmaxf(sh[m],sh[m+s]); __syncthreads(); }
    float mxw = sh[0]; __syncthreads();
    float ew = expf(sw - mxw);
    sh[m] = ew; __syncthreads();
    for (int s=32;s>0;s>>=1){ if(m<s) sh[m]+=sh[m+s]; __syncthreads(); }
    float sumw = sh[0]; __syncthreads();
    g_simw[row] = ew / sumw;
}

// ---------------- sub_vec = sum_m sub_memory * sim_r -----------------------------------
__global__ void subvec_k(const float* __restrict__ sub) {
    int b = blockIdx.x, d = threadIdx.x;
    __shared__ float ss[64];
    if (d < 64) ss[d] = g_simr[b*64 + d];
    __syncthreads();
    const float* base = sub + (size_t)b*64*512 + d;
    float acc = 0.f;
#pragma unroll
    for (int m=0;m<64;m++) acc += base[m*512] * ss[m];
    g_subvec[b*512 + d] = acc;
}

// ---------------- launch -------------------------------------------------------------------
extern "C" void kernel_launch(void* const* d_in, const int* in_sizes, int n_in,
                              void* d_out, int out_size)
{
    const float* x    = (const float*)d_in[0];
    const float* sub  = (const float*)d_in[1];
    const float* W1r  = (const float*)d_in[2];
    const float* b1r  = (const float*)d_in[3];
    const float* W2r  = (const float*)d_in[4];
    const float* W1w  = (const float*)d_in[6];
    const float* b1w  = (const float*)d_in[7];
    const float* W2w  = (const float*)d_in[8];
    const float* Wf   = (const float*)d_in[10];
    const float* bf   = (const float*)d_in[11];
    const float* Wi   = (const float*)d_in[12];
    const float* bi   = (const float*)d_in[13];
    const float* Wc   = (const float*)d_in[14];
    const float* bc   = (const float*)d_in[15];
    const float* Wsub = (const float*)d_in[16];
    const float* bsub = (const float*)d_in[17];
    const float* Wfin = (const float*)d_in[18];
    const float* bfin = (const float*)d_in[19];
    float* out = (float*)d_out;

    cudaFuncSetAttribute(gemm_t, cudaFuncAttributeMaxDynamicSharedMemorySize, SMEM_BYTES);

    prep_k<<<(NC*Dd + 255)/256, 256>>>(W1r, W1w, Wf, Wi, Wc, b1r, b1w, bf, bi, bc);

    // xterm = x @ WX^T + bstack
    gemm_t<<<dim3(NC/BN, Bb/BM), 128, SMEM_BYTES>>>(0, x, nullptr, g_bstack, nullptr, nullptr, nullptr);

    // main: sub_memory @ Wbig^T + xterm -> score partials, F, P
    gemm_t<<<dim3(NC/BN, NROWS/BM), 128, SMEM_BYTES>>>(1, sub, nullptr, nullptr, W2r, W2w, nullptr);

    softmax_k<<<Bb, 64>>>();
    subvec_k<<<Bb, 512>>>(sub);

    // read_vec = tanh(sub_vec @ Wfin^T + bfin) -> out[b,0,:]
    gemm_t<<<dim3(Dd/BN, Bb/BM), 128, SMEM_BYTES>>>(2, nullptr, Wfin, bfin, nullptr, nullptr, out);

    // new_mem = tanh(((1-sw*F)*sub + P*sw) @ Wsub^T + bsub) -> out[b,1+m,:]  (gating fused)
    gemm_t<<<dim3(Dd/BN, NROWS/BM), 128, SMEM_BYTES>>>(3, sub, Wsub, bsub, nullptr, nullptr, out);
}

// round 15
// speedup vs baseline: 1.0925x; 1.0925x over previous
#include <cuda_runtime.h>
#include <math.h>
#include <stdint.h>

#define Bb 2048
#define Mm 64
#define Dd 512
#define NROWS (Bb*Mm)     // 131072
#define NC    2560        // stacked cols: [zr | zw | zF | interleaved(zI,zC)]
#define BM    128
#define BN    128
#define BK    32
#define NKC   (Dd/BK)     // 16
#define STG   3
#define PAD   36          // floats per smem row (144B; conflict-free LDSM)
#define ASTG  (128*PAD)   // 4608 floats
#define BSTG  (128*PAD)   // 4608 floats
#define XTSOFF (STG*(ASTG+BSTG))          // 27648 floats; epilogue staging beyond buffers
#define SMEM_BYTES ((XTSOFF + 384)*4)     // 112128 B -> still 2 CTAs/SM

// ---------------- scratch (device globals) -----------------------------------------
__device__ float g_Wbig [NC*Dd];
__device__ float g_WbigX[NC*Dd];
__device__ float g_bstack[NC];
__device__ float g_xterm[Bb*NC];
__device__ float g_F[(size_t)NROWS*Dd];
__device__ float g_P[(size_t)NROWS*Dd];      // sigmoid(zI)*tanh(zC)
__device__ float g_subvec[Bb*Dd];
__device__ float g_sRp[(size_t)NROWS*16];
__device__ float g_sWp[(size_t)NROWS*16];
__device__ float g_simr[NROWS];
__device__ float g_simw[NROWS];

__device__ __forceinline__ uint32_t smem_u32(const void* p){
    uint32_t a;
    asm("{ .reg .u64 t; cvta.to.shared.u64 t, %1; cvt.u32.u64 %0, t; }" : "=r"(a) : "l"(p));
    return a;
}
__device__ __forceinline__ float fsig(float z){ return __fdividef(1.f, 1.f + __expf(-z)); }
__device__ __forceinline__ float ftanh(float z){ return __fdividef(2.f, 1.f + __expf(-2.f*z)) - 1.f; }
__device__ __forceinline__ void ldmx4(uint32_t* r, uint32_t addr){
    asm volatile("ldmatrix.sync.aligned.m8n8.x4.shared.b16 {%0,%1,%2,%3}, [%4];"
        : "=r"(r[0]), "=r"(r[1]), "=r"(r[2]), "=r"(r[3]) : "r"(addr));
}
__device__ __forceinline__ void mma8(float* d, const uint32_t* a, const uint32_t* b){
    asm volatile(
        "mma.sync.aligned.m16n8k8.row.col.f32.tf32.tf32.f32 "
        "{%0,%1,%2,%3}, {%4,%5,%6,%7}, {%8,%9}, {%0,%1,%2,%3};"
        : "+f"(d[0]), "+f"(d[1]), "+f"(d[2]), "+f"(d[3])
        : "r"(a[0]), "r"(a[1]), "r"(a[2]), "r"(a[3]), "r"(b[0]), "r"(b[1]));
}

// ---------------- weight stacking: [Wr | Ww | WF | interleave(WI,WC)] ----------------
__global__ void prep_k(const float* __restrict__ W1r, const float* __restrict__ W1w,
                       const float* __restrict__ Wf,  const float* __restrict__ Wi,
                       const float* __restrict__ Wc,
                       const float* __restrict__ b1r, const float* __restrict__ b1w,
                       const float* __restrict__ bf,  const float* __restrict__ bi,
                       const float* __restrict__ bc)
{
    int i = blockIdx.x*blockDim.x + threadIdx.x;
    if (i < NC*Dd) {
        int c = i >> 9, k = i & 511;
        const float* W; int d;
        if (c < 1536) { int j = c >> 9; d = c & 511; W = (j==0)?W1r:(j==1)?W1w:Wf; }
        else          { int t = c - 1536; d = t >> 1; W = (t&1)?Wc:Wi; }
        g_Wbig[i]  = W[d*(2*Dd) + k];
        g_WbigX[i] = W[d*(2*Dd) + Dd + k];
        if (i < NC) {
            const float* bb; int db;
            if (i < 1536) { int j = i >> 9; db = i & 511; bb = (j==0)?b1r:(j==1)?b1w:bf; }
            else          { int t = i - 1536; db = t >> 1; bb = (t&1)?bc:bi; }
            g_bstack[i] = bb[db];
        }
    }
}

// ---------------- tf32 mma.sync GEMM, 64x32 warp tiles, 2 CTAs/SM ---------------------
// epi 0: xterm   epi 1: main (scores / F / P)   epi 2: fin->out
// epi 3: sub->out with FUSED gating in the A loader (sw preloaded in registers)
__global__ void __launch_bounds__(256,2)
gemm_t(int epi, const float* __restrict__ Aext, const float* __restrict__ Bext,
       const float* __restrict__ bias,
       const float* __restrict__ w2r, const float* __restrict__ w2w,
       float* __restrict__ out)
{
    extern __shared__ float sm[];
    const uint32_t s0 = smem_u32(sm);

    const int tid  = threadIdx.x;
    const int lane = tid & 31, wid = tid >> 5;
    const int wm = wid & 1, wn = wid >> 1;        // 2x4 warp grid, warp tile 64x32
    const int qrow = lane >> 2;
    const int qcol = (lane & 3) * 2;
    const int row0 = blockIdx.y * BM;
    const int n0   = blockIdx.x * BN;
    const int jt   = n0 >> 9;                     // epi1: 0,1=scores(r,w) 2=F 3,4=IC

    const float* A  = (epi==2) ? g_subvec : Aext;
    const float* Bw = (epi==0) ? g_WbigX : (epi==1) ? g_Wbig : Bext;

    const float* Arow = A  + (size_t)row0 * Dd;
    const float* Brow = Bw + (size_t)n0   * Dd;

    float* xts = sm + XTSOFF;        // [2][128] xterm slices
    float* w2s = sm + XTSOFF + 256;  // [128]

    // pre-stage epilogue inputs BEFORE mainloop (mainloop barriers make them visible)
    if (epi == 1) {
        int bloc = tid >> 7, cl = tid & 127;
        xts[tid] = g_xterm[(size_t)((row0 >> 6) + bloc) * NC + n0 + cl];
        if (jt < 2 && tid < 128) w2s[tid] = ((jt==0)?w2r:w2w)[(n0 & 511) + tid];
    }

    // epi3: per-thread simw preload (rows fixed across chunks; no barrier needed)
    float swreg[4];
    if (epi == 3) {
#pragma unroll
        for (int j=0;j<4;j++)
            swreg[j] = __ldg(g_simw + row0 + j*32 + (tid >> 3));
    }

    float acc[4][4][4];
#pragma unroll
    for (int mt=0;mt<4;mt++)
#pragma unroll
        for (int nt=0;nt<4;nt++)
#pragma unroll
            for (int q=0;q<4;q++) acc[mt][nt][q]=0.f;

    uint32_t offA[4], offB[2];
#pragma unroll
    for (int mt=0;mt<4;mt++)
        offA[mt] = (uint32_t)(((wm*64 + mt*16 + (lane&15))*PAD + ((lane>>4)<<2)) * 4);
#pragma unroll
    for (int p=0;p<2;p++)
        offB[p] = (uint32_t)(((wn*32 + p*16 + (((lane>>4)&1)<<3) + (lane&7))*PAD
                              + (((lane>>3)&1)<<2)) * 4);

// A tile via cp.async: 128 rows x 32 floats (4 float4 per thread)
#define LOADA(kc, slot) do {                                                     \
    int k0 = (kc)*BK;                                                            \
    _Pragma("unroll")                                                            \
    for (int j=0;j<4;j++){                                                       \
        int idx = j*256 + tid;                                                   \
        int r = idx >> 3, seg = idx & 7;                                         \
        const float* ga = Arow + (size_t)r*Dd + k0 + seg*4;                      \
        uint32_t sa = s0 + (uint32_t)(((slot)*ASTG + r*PAD + seg*4)*4);          \
        asm volatile("cp.async.cg.shared.global [%0],[%1],16;" :: "r"(sa), "l"(ga)); \
    } } while(0)

// A tile with fused gating (epi == 3): mem = (1 - sw*F)*sub + P*sw via LDG + STS
#define LOADA3(kc, slot) do {                                                    \
    int k0 = (kc)*BK;                                                            \
    _Pragma("unroll")                                                            \
    for (int j=0;j<4;j++){                                                       \
        int idx = j*256 + tid;                                                   \
        int r = idx >> 3, seg = idx & 7;                                         \
        size_t goff = (size_t)(row0 + r)*Dd + k0 + seg*4;                        \
        float swv = swreg[j];                                                    \
        float4 s4 = *(const float4*)(Arow + (size_t)r*Dd + k0 + seg*4);          \
        float4 fv = *(const float4*)(g_F + goff);                                \
        float4 pv = *(const float4*)(g_P + goff);                                \
        float4 o;                                                                \
        o.x = (1.f - swv*fv.x)*s4.x + pv.x*swv;                                  \
        o.y = (1.f - swv*fv.y)*s4.y + pv.y*swv;                                  \
        o.z = (1.f - swv*fv.z)*s4.z + pv.z*swv;                                  \
        o.w = (1.f - swv*fv.w)*s4.w + pv.w*swv;                                  \
        *(float4*)(sm + (slot)*ASTG + r*PAD + seg*4) = o;                        \
    } } while(0)

#define LOADB(kc, slot) do {                                                     \
    int k0 = (kc)*BK;                                                            \
    _Pragma("unroll")                                                            \
    for (int j=0;j<4;j++){                                                       \
        int idx = j*256 + tid;                                                   \
        int r = idx >> 3, seg = idx & 7;                                         \
        const float* gb = Brow + (size_t)r*Dd + k0 + seg*4;                      \
        uint32_t sb = s0 + (uint32_t)(((STG*ASTG) + (slot)*BSTG + r*PAD + seg*4)*4); \
        asm volatile("cp.async.cg.shared.global [%0],[%1],16;" :: "r"(sb), "l"(gb)); \
    }                                                                            \
    asm volatile("cp.async.commit_group;" ::: "memory");                         \
} while(0)

    if (epi != 3) LOADA(0,0); else LOADA3(0,0);
    LOADB(0,0);
    if (epi != 3) LOADA(1,1); else LOADA3(1,1);
    LOADB(1,1);

    int slot = 0;
    for (int i = 0; i < NKC; i++) {
        if (i + 2 < NKC) { asm volatile("cp.async.wait_group 1;" ::: "memory"); }
        else             { asm volatile("cp.async.wait_group 0;" ::: "memory"); }
        __syncthreads();
        if (i + 2 < NKC) {
            int ns = slot + 2; if (ns >= STG) ns -= STG;
            if (epi != 3) LOADA(i+2, ns); else LOADA3(i+2, ns);
            LOADB(i+2, ns);
        }

        uint32_t abase = s0 + (uint32_t)(slot*ASTG*4);
        uint32_t bbase = s0 + (uint32_t)((STG*ASTG + slot*BSTG)*4);
#pragma unroll
        for (int s = 0; s < 4; s++) {               // four k8 steps
            uint32_t a[4][4], bt[2][4];
#pragma unroll
            for (int mt=0;mt<4;mt++) ldmx4(a[mt], abase + offA[mt] + s*32);
#pragma unroll
            for (int p=0;p<2;p++)    ldmx4(bt[p], bbase + offB[p] + s*32);
#pragma unroll
            for (int mt=0;mt<4;mt++)
#pragma unroll
                for (int p=0;p<2;p++){
                    mma8(acc[mt][2*p],   a[mt], &bt[p][0]);
                    mma8(acc[mt][2*p+1], a[mt], &bt[p][2]);
                }
        }
        if (++slot >= STG) slot = 0;
    }
#undef LOADA
#undef LOADA3
#undef LOADB

    // ---------------- epilogue (xts/w2s pre-staged; mainloop syncs ordered them) -------
    if (epi == 1 && jt < 2) {
        float* dstp = (jt == 0) ? g_sRp : g_sWp;
        const int pidx = ((n0 & 511) >> 7) * 4 + wn;      // 0..15
        const float* x0 = xts + wm * 128;
#pragma unroll
        for (int mt=0;mt<4;mt++){
            int r0g = row0 + wm*64 + mt*16 + qrow;
            float sp0 = 0.f, sp1 = 0.f;
#pragma unroll
            for (int nt=0;nt<4;nt++){
                int cl = wn*32 + nt*8 + qcol;
                float w0 = w2s[cl], w1 = w2s[cl+1];
                sp0 += fmaxf(acc[mt][nt][0]+x0[cl],0.f)*w0 + fmaxf(acc[mt][nt][1]+x0[cl+1],0.f)*w1;
                sp1 += fmaxf(acc[mt][nt][2]+x0[cl],0.f)*w0 + fmaxf(acc[mt][nt][3]+x0[cl+1],0.f)*w1;
            }
            sp0 += __shfl_xor_sync(0xffffffffu, sp0, 1);
            sp0 += __shfl_xor_sync(0xffffffffu, sp0, 2);
            sp1 += __shfl_xor_sync(0xffffffffu, sp1, 1);
            sp1 += __shfl_xor_sync(0xffffffffu, sp1, 2);
            if ((lane & 3) == 0) {
                dstp[(size_t)r0g*16 + pidx]     = sp0;
                dstp[(size_t)(r0g+8)*16 + pidx] = sp1;
            }
        }
        return;
    }

#pragma unroll
    for (int mt=0;mt<4;mt++){
        int r0g = row0 + wm*64 + mt*16 + qrow;
#pragma unroll
        for (int h=0;h<2;h++){
            int row = r0g + h*8;
#pragma unroll
            for (int nt=0;nt<4;nt++){
                int cl = wn*32 + nt*8 + qcol;
                int cg = n0 + cl;
                float c0 = acc[mt][nt][h*2+0];
                float c1 = acc[mt][nt][h*2+1];
                if (epi == 0) {
                    float2 o = { c0 + bias[cg], c1 + bias[cg+1] };
                    *(float2*)(g_xterm + (size_t)row*NC + cg) = o;
                } else if (epi == 1) {
                    const float* xr = xts + wm * 128;
                    float z0 = c0 + xr[cl];
                    float z1 = c1 + xr[cl+1];
                    if (jt == 2) {
                        float2 o = { fsig(z0), fsig(z1) };
                        *(float2*)(g_F + (size_t)row*Dd + (cg - 1024)) = o;
                    } else {
                        g_P[(size_t)row*Dd + ((cg - 1536) >> 1)] = fsig(z0) * ftanh(z1);
                    }
                } else {
                    size_t ob = (epi == 2) ? (size_t)row * (65*Dd)
                                           : ((size_t)(row >> 6) * 65 + 1 + (row & 63)) * Dd;
                    float2 o = { ftanh(c0 + bias[cg]), ftanh(c1 + bias[cg+1]) };
                    *(float2*)(out + ob + cg) = o;
                }
            }
        }
    }
}

// ---------------- softmax over M=64 ---------------------------------------------------
__global__ void softmax_k() {
    int b = blockIdx.x, m = threadIdx.x;
    int row = b*64 + m;
    float sr = 0.f, sw = 0.f;
#pragma unroll
    for (int p=0;p<16;p++){ sr += g_sRp[(size_t)row*16+p]; sw += g_sWp[(size_t)row*16+p]; }

    __shared__ float sh[64];
    sh[m] = sr; __syncthreads();
    for (int s=32;s>0;s>>=1){ if(m<s) sh[m]=fmaxf(sh[m],sh[m+s]); __syncthreads(); }
    float mxr = sh[0]; __syncthreads();
    float er = expf(sr - mxr);
    sh[m] = er; __syncthreads();
    for (int s=32;s>0;s>>=1){ if(m<s) sh[m]+=sh[m+s]; __syncthreads(); }
    float sumr = sh[0]; __syncthreads();
    g_simr[row] = er / sumr;

    sh[m] = sw; __syncthreads();
    for (int s=32;s>0;s>>=1){ if(m<s) sh[m]=fmaxf(sh[m],sh[m+s]); __syncthreads(); }
    float mxw = sh[0]; __syncthreads();
    float ew = expf(sw - mxw);
    sh[m] = ew; __syncthreads();
    for (int s=32;s>0;s>>=1){ if(m<s) sh[m]+=sh[m+s]; __syncthreads(); }
    float sumw = sh[0]; __syncthreads();
    g_simw[row] = ew / sumw;
}

// ---------------- sub_vec = sum_m sub_memory * sim_r -----------------------------------
__global__ void subvec_k(const float* __restrict__ sub) {
    int b = blockIdx.x, d = threadIdx.x;
    __shared__ float ss[64];
    if (d < 64) ss[d] = g_simr[b*64 + d];
    __syncthreads();
    const float* base = sub + (size_t)b*64*512 + d;
    float acc = 0.f;
#pragma unroll
    for (int m=0;m<64;m++) acc += base[m*512] * ss[m];
    g_subvec[b*512 + d] = acc;
}

// ---------------- launch -------------------------------------------------------------------
extern "C" void kernel_launch(void* const* d_in, const int* in_sizes, int n_in,
                              void* d_out, int out_size)
{
    const float* x    = (const float*)d_in[0];
    const float* sub  = (const float*)d_in[1];
    const float* W1r  = (const float*)d_in[2];
    const float* b1r  = (const float*)d_in[3];
    const float* W2r  = (const float*)d_in[4];
    const float* W1w  = (const float*)d_in[6];
    const float* b1w  = (const float*)d_in[7];
    const float* W2w  = (const float*)d_in[8];
    const float* Wf   = (const float*)d_in[10];
    const float* bf   = (const float*)d_in[11];
    const float* Wi   = (const float*)d_in[12];
    const float* bi   = (const float*)d_in[13];
    const float* Wc   = (const float*)d_in[14];
    const float* bc   = (const float*)d_in[15];
    const float* Wsub = (const float*)d_in[16];
    const float* bsub = (const float*)d_in[17];
    const float* Wfin = (const float*)d_in[18];
    const float* bfin = (const float*)d_in[19];
    float* out = (float*)d_out;

    cudaFuncSetAttribute(gemm_t, cudaFuncAttributeMaxDynamicSharedMemorySize, SMEM_BYTES);

    prep_k<<<(NC*Dd + 255)/256, 256>>>(W1r, W1w, Wf, Wi, Wc, b1r, b1w, bf, bi, bc);

    // xterm = x @ WX^T + bstack
    gemm_t<<<dim3(NC/BN, Bb/BM), 256, SMEM_BYTES>>>(0, x, nullptr, g_bstack, nullptr, nullptr, nullptr);

    // main: sub_memory @ Wbig^T + xterm -> score partials, F, P
    gemm_t<<<dim3(NC/BN, NROWS/BM), 256, SMEM_BYTES>>>(1, sub, nullptr, nullptr, W2r, W2w, nullptr);

    softmax_k<<<Bb, 64>>>();
    subvec_k<<<Bb, 512>>>(sub);

    // read_vec = tanh(sub_vec @ Wfin^T + bfin) -> out[b,0,:]
    gemm_t<<<dim3(Dd/BN, Bb/BM), 256, SMEM_BYTES>>>(2, nullptr, Wfin, bfin, nullptr, nullptr, out);

    // new_mem = tanh(((1-sw*F)*sub + P*sw) @ Wsub^T + bsub) -> out[b,1+m,:]  (gating fused)
    gemm_t<<<dim3(Dd/BN, NROWS/BM), 256, SMEM_BYTES>>>(3, sub, Wsub, bsub, nullptr, nullptr, out);
}